// round 10
// baseline (speedup 1.0000x reference)
#include <cuda_runtime.h>
#include <stdint.h>

#define HH 128
#define WW 160
#define HWSZ (HH * WW)          // 20480
#define BMAX 4
#define FLOW_SCALE 160.0f

#define TBITS 20
#define TSIZE (1u << TBITS)
#define TMASK (TSIZE - 1u)
__device__ uint32_t g_hash[(size_t)BMAX * TSIZE];         // 16 MB, L2-resident
// Packed accumulator: low 32 = event count, high 32 = distinct-src count.
__device__ unsigned long long g_acc[BMAX * 2 * HWSZ];     // 1.25 MB
__device__ float2   g_flow2[BMAX * HWSZ];                 // interleaved (fx, fy)

// Region sizes for the single-pass prep (one store per thread).
#define PREP_N4   ((int)((size_t)BMAX * TSIZE / 4))       // 1,048,576 uint4 stores
#define PREP_NA2  (BMAX * 2 * HWSZ / 2)                   // 81,920 ulonglong2 stores
#define PREP_NF2(B) ((B) * HWSZ / 2)                      // float2-pair interleaves

// ---------------------------------------------------------------------------
// Single-pass prep: exactly one store per thread (no grid-stride loops).
// ---------------------------------------------------------------------------
__global__ void prep_kernel(const float* __restrict__ flow, int nf2) {
    int tid = blockIdx.x * blockDim.x + threadIdx.x;

    if (tid < PREP_N4) {
        reinterpret_cast<uint4*>(g_hash)[tid] = make_uint4(0u, 0u, 0u, 0u);
        return;
    }
    tid -= PREP_N4;
    if (tid < PREP_NA2) {
        reinterpret_cast<ulonglong2*>(g_acc)[tid] = make_ulonglong2(0ull, 0ull);
        return;
    }
    tid -= PREP_NA2;
    if (tid < nf2) {
        int j2 = tid * 2;
        int b  = j2 / HWSZ;          // const divisor -> mul/shift
        int j  = j2 - b * HWSZ;
        const float* fb = flow + (size_t)b * 2 * HWSZ;
        float2 fx2 = *reinterpret_cast<const float2*>(fb + j);         // fx[j], fx[j+1]
        float2 fy2 = *reinterpret_cast<const float2*>(fb + HWSZ + j);  // fy[j], fy[j+1]
        float2* dst = g_flow2 + (size_t)b * HWSZ + j;
        dst[0] = make_float2(fx2.x, fy2.x);
        dst[1] = make_float2(fx2.y, fy2.y);
    }
}

// ---------------------------------------------------------------------------
// Per-event: lean body. batch = blockIdx.y; 2 contiguous events per thread.
// ---------------------------------------------------------------------------
__global__ void __launch_bounds__(256)
event_kernel(const float4* __restrict__ events, int N) {
    const int b = blockIdx.y;
    const int base = (blockIdx.x * blockDim.x + threadIdx.x) * 2;

    const float4* ev = events + (size_t)b * N;
    const float2* fl = g_flow2 + (size_t)b * HWSZ;
    uint32_t* tbl = g_hash + ((size_t)b << TBITS);
    unsigned long long* accb = g_acc + (size_t)b * 2 * HWSZ;

#pragma unroll
    for (int k = 0; k < 2; k++) {
        int i = base + k;
        if (i >= N) return;

        float4 e = ev[i];               // (t, y, x, p)
        float t = e.x, y = e.y, x = e.z, p = e.w;

        int src = (int)(__fadd_rn(__fmul_rn(y, (float)WW), x));

        float2 f = __ldg(&fl[src]);     // (fx, fy)

        // warped = yx + (1-t) * flow * 160  (exact ref op order, no FMA)
        float s  = __fadd_rn(1.0f, -t);
        float wy = __fadd_rn(y, __fmul_rn(__fmul_rn(s, f.y), FLOW_SCALE));
        float wx = __fadd_rn(x, __fmul_rn(__fmul_rn(s, f.x), FLOW_SCALE));

        // round half-to-even directly to int (F2I.RN); saturation makes
        // out-of-range values fail the unsigned bounds check below.
        int iy = __float2int_rn(wy);
        int ix = __float2int_rn(wx);

        if (((unsigned)iy >= (unsigned)HH) | ((unsigned)ix >= (unsigned)WW))
            continue;

        int fw = iy * WW + ix;
        uint32_t c = __float_as_uint(p) >> 31;   // p==+1 -> 0 (pos), p==-1 -> 1 (neg)

        // hash dedup: direct CAS (slots go 0 -> tag exactly once)
        uint32_t key = (c << 30) | ((uint32_t)src << 15) | (uint32_t)fw;
        uint32_t tag = key + 1u;
        uint32_t h   = (key * 2654435761u) >> (32 - TBITS);

        unsigned long long inc = 1ull;
        while (true) {
            uint32_t old = atomicCAS(&tbl[h], 0u, tag);
            if (old == 0u) { inc = 0x100000001ull; break; }  // first occurrence
            if (old == tag) break;                           // duplicate
            h = (h + 1u) & TMASK;
        }

        atomicAdd(&accb[(size_t)c * HWSZ + fw], inc);
    }
}

// ---------------------------------------------------------------------------
// Final: out = contrib>0 ? cnt/contrib : 0
// ---------------------------------------------------------------------------
__global__ void div_kernel(float* __restrict__ out, int n) {
    int i = blockIdx.x * blockDim.x + threadIdx.x;
    if (i >= n) return;
    unsigned long long v = g_acc[i];
    uint32_t cnt = (uint32_t)v;
    uint32_t ctb = (uint32_t)(v >> 32);
    out[i] = (ctb > 0u) ? ((float)cnt / (float)ctb) : 0.0f;
}

extern "C" void kernel_launch(void* const* d_in, const int* in_sizes, int n_in,
                              void* d_out, int out_size) {
    const float*  flow   = (const float*)d_in[0];   // (B, 2, H, W)
    const float4* events = (const float4*)d_in[1];  // (B, N, 4)
    float* out = (float*)d_out;                     // (B, 2, H, W)

    int B = in_sizes[0] / (2 * HWSZ);
    if (B > BMAX) B = BMAX;
    int N = in_sizes[1] / (4 * B);

    int nf2 = PREP_NF2(B);
    int prep_threads = PREP_N4 + PREP_NA2 + nf2;
    prep_kernel<<<(prep_threads + 255) / 256, 256>>>(flow, nf2);

    dim3 grid((N + 511) / 512, B);
    event_kernel<<<grid, 256>>>(events, N);

    int dn = B * 2 * HWSZ;
    div_kernel<<<(dn + 255) / 256, 256>>>(out, dn);
}

// round 15
// speedup vs baseline: 1.0102x; 1.0102x over previous
#include <cuda_runtime.h>
#include <stdint.h>

#define HH 128
#define WW 160
#define HWSZ (HH * WW)          // 20480
#define BMAX 4
#define FLOW_SCALE 160.0f

#define TBITS 20
#define TSIZE (1u << TBITS)
#define TMASK (TSIZE - 1u)
__device__ uint32_t g_hash[(size_t)BMAX * TSIZE];         // 16 MB, L2-resident
// Packed accumulator: low 32 = event count, high 32 = distinct-src count.
__device__ unsigned long long g_acc[BMAX * 2 * HWSZ];     // 1.25 MB
__device__ float2   g_flow2[BMAX * HWSZ];                 // interleaved (fx, fy)

#define PREP_N4   ((int)((size_t)BMAX * TSIZE / 4))       // 1,048,576 uint4
#define PREP_NA2  (BMAX * 2 * HWSZ / 2)                   // 81,920 ulonglong2
#define PREP_BLOCKS 1184
#define PREP_T      256
#define PREP_STRIDE (PREP_BLOCKS * PREP_T)                // 303,104 = one full wave

// ---------------------------------------------------------------------------
// Single-wave prep: zero hash + acc, build interleaved flow (fx, fy).
// ---------------------------------------------------------------------------
__global__ void __launch_bounds__(PREP_T)
prep_kernel(const float* __restrict__ flow, int nf2) {
    int tid = blockIdx.x * PREP_T + threadIdx.x;

    uint4* hm = reinterpret_cast<uint4*>(g_hash);
    uint4 z4 = make_uint4(0u, 0u, 0u, 0u);
    for (int i = tid; i < PREP_N4; i += PREP_STRIDE) hm[i] = z4;

    ulonglong2* am = reinterpret_cast<ulonglong2*>(g_acc);
    if (tid < PREP_NA2) am[tid] = make_ulonglong2(0ull, 0ull);

    if (tid < nf2) {                     // nf2 = B*HWSZ/2 (pairs of pixels)
        int j2 = tid * 2;
        int b  = j2 / HWSZ;
        int j  = j2 - b * HWSZ;
        const float* fb = flow + (size_t)b * 2 * HWSZ;
        float2 fx2 = *reinterpret_cast<const float2*>(fb + j);         // fx[j], fx[j+1]
        float2 fy2 = *reinterpret_cast<const float2*>(fb + HWSZ + j);  // fy[j], fy[j+1]
        float2* dst = g_flow2 + (size_t)b * HWSZ + j;
        dst[0] = make_float2(fx2.x, fy2.x);   // (fx, fy) — matches event body
        dst[1] = make_float2(fx2.y, fy2.y);
    }
}

// ---------------------------------------------------------------------------
// Per-event: lean body (identical to R10, numerically exact).
// ---------------------------------------------------------------------------
__global__ void __launch_bounds__(256)
event_kernel(const float4* __restrict__ events, int N) {
    const int b = blockIdx.y;
    const int base = (blockIdx.x * blockDim.x + threadIdx.x) * 2;

    const float4* ev = events + (size_t)b * N;
    const float2* fl = g_flow2 + (size_t)b * HWSZ;
    uint32_t* tbl = g_hash + ((size_t)b << TBITS);
    unsigned long long* accb = g_acc + (size_t)b * 2 * HWSZ;

#pragma unroll
    for (int k = 0; k < 2; k++) {
        int i = base + k;
        if (i >= N) return;

        float4 e = ev[i];               // (t, y, x, p)
        float t = e.x, y = e.y, x = e.z, p = e.w;

        int src = (int)(__fadd_rn(__fmul_rn(y, (float)WW), x));

        float2 f = __ldg(&fl[src]);     // (fx, fy)

        // warped = yx + (1-t) * flow * 160  (exact ref op order, no FMA)
        float s  = __fadd_rn(1.0f, -t);
        float wy = __fadd_rn(y, __fmul_rn(__fmul_rn(s, f.y), FLOW_SCALE));
        float wx = __fadd_rn(x, __fmul_rn(__fmul_rn(s, f.x), FLOW_SCALE));

        // round half-to-even directly to int (F2I.RN); saturation makes
        // out-of-range values fail the unsigned bounds check below.
        int iy = __float2int_rn(wy);
        int ix = __float2int_rn(wx);

        if (((unsigned)iy >= (unsigned)HH) | ((unsigned)ix >= (unsigned)WW))
            continue;

        int fw = iy * WW + ix;
        uint32_t c = __float_as_uint(p) >> 31;   // p==+1 -> 0 (pos), p==-1 -> 1 (neg)

        // hash dedup: direct CAS (slots go 0 -> tag exactly once)
        uint32_t key = (c << 30) | ((uint32_t)src << 15) | (uint32_t)fw;
        uint32_t tag = key + 1u;
        uint32_t h   = (key * 2654435761u) >> (32 - TBITS);

        unsigned long long inc = 1ull;
        while (true) {
            uint32_t old = atomicCAS(&tbl[h], 0u, tag);
            if (old == 0u) { inc = 0x100000001ull; break; }  // first occurrence
            if (old == tag) break;                           // duplicate
            h = (h + 1u) & TMASK;
        }

        atomicAdd(&accb[(size_t)c * HWSZ + fw], inc);
    }
}

// ---------------------------------------------------------------------------
// Final: out = contrib>0 ? cnt/contrib : 0
// ---------------------------------------------------------------------------
__global__ void div_kernel(float* __restrict__ out, int n) {
    int i = blockIdx.x * blockDim.x + threadIdx.x;
    if (i >= n) return;
    unsigned long long v = g_acc[i];
    uint32_t cnt = (uint32_t)v;
    uint32_t ctb = (uint32_t)(v >> 32);
    out[i] = (ctb > 0u) ? ((float)cnt / (float)ctb) : 0.0f;
}

extern "C" void kernel_launch(void* const* d_in, const int* in_sizes, int n_in,
                              void* d_out, int out_size) {
    const float*  flow   = (const float*)d_in[0];   // (B, 2, H, W)
    const float4* events = (const float4*)d_in[1];  // (B, N, 4)
    float* out = (float*)d_out;                     // (B, 2, H, W)

    int B = in_sizes[0] / (2 * HWSZ);
    if (B > BMAX) B = BMAX;
    int N = in_sizes[1] / (4 * B);

    prep_kernel<<<PREP_BLOCKS, PREP_T>>>(flow, B * HWSZ / 2);

    dim3 grid((N + 511) / 512, B);
    event_kernel<<<grid, 256>>>(events, N);

    int dn = B * 2 * HWSZ;
    div_kernel<<<(dn + 255) / 256, 256>>>(out, dn);
}